// round 2
// baseline (speedup 1.0000x reference)
#include <cuda_runtime.h>

// MultiScaleEdgeBuilder: B=64 graphs, 256 nodes each, all ordered intra-graph
// pairs (i != j). Output (float32, concatenated):
//   [0, 2E)    edge_index  (row indices, then col indices)
//   [2E, 18E)  edge_attr   (zeros, EDGE_DIM=16)
//   [18E, 21E) rbf         exp(-d^2 / c^2), c in {4, 8, 12}
// E = 64 * 256 * 255 = 4,177,920.  Pure HBM-write-bound streaming kernel.

#define NPER    256
#define NGRAPH  64
#define EPG     (NPER * (NPER - 1))      // 65280 edges per graph
#define E_TOTAL (NGRAPH * EPG)           // 4,177,920

__global__ __launch_bounds__(256, 8)
void MultiScaleEdgeBuilder_kernel(const float* __restrict__ pos,
                                  float* __restrict__ out) {
    int t = blockIdx.x * 256 + threadIdx.x;   // 0 .. 64*65536-1
    int g = t >> 16;                          // graph id
    int w = t & 65535;                        // cell within graph (i*256 + j)
    int i = w >> 8;
    int j = w & 255;
    if (i == j) return;                       // diagonal: no edge

    int row = (g << 8) + i;
    int col = (g << 8) + j;
    // compacted edge index matching np.nonzero(~eye(256)) row-major order
    int e = g * EPG + i * 255 + j - (j > i);

    // pos is [N,3] float32. Row load is warp-uniform (broadcast from L1);
    // col loads are contiguous across the warp.
    const float* pr = pos + 3 * row;
    const float* pc = pos + 3 * col;
    float dx = pr[0] - pc[0];
    float dy = pr[1] - pc[1];
    float dz = pr[2] - pc[2];
    float d2 = dx * dx + dy * dy + dz * dz;

    // rbf = exp(-(d/c)^2) = exp(-d2 / c^2); no sqrt needed.
    float r0 = __expf(-d2 * (1.0f / 16.0f));    // c = 4
    float r1 = __expf(-d2 * (1.0f / 64.0f));    // c = 8
    float r2 = __expf(-d2 * (1.0f / 144.0f));   // c = 12

    // edge_index (as float; values <= 16383, exact in fp32)
    out[e]           = (float)row;
    out[E_TOTAL + e] = (float)col;

    // edge_attr zeros: 16 floats, 4x float4 (16B aligned: 2E%4==0, 16e%4==0)
    float4 z = make_float4(0.f, 0.f, 0.f, 0.f);
    float4* zp = (float4*)(out + 2 * E_TOTAL + 16 * e);
    zp[0] = z; zp[1] = z; zp[2] = z; zp[3] = z;

    // rbf [E,3]
    float* rp = out + 18 * E_TOTAL + 3 * e;
    rp[0] = r0; rp[1] = r1; rp[2] = r2;
}

extern "C" void kernel_launch(void* const* d_in, const int* in_sizes, int n_in,
                              void* d_out, int out_size) {
    const float* pos = (const float*)d_in[0];   // [16384, 3] float32
    float* out = (float*)d_out;                 // 21 * E floats

    // 64 graphs * 65536 cells = 4,194,304 threads -> 16384 blocks of 256
    MultiScaleEdgeBuilder_kernel<<<16384, 256>>>(pos, out);
}

// round 3
// speedup vs baseline: 1.5447x; 1.5447x over previous
#include <cuda_runtime.h>

// MultiScaleEdgeBuilder: B=64 graphs, 256 nodes each, all ordered intra-graph
// pairs (i != j). Output (float32, concatenated):
//   [0, 2E)    edge_index  (row indices, then col indices)
//   [2E, 18E)  edge_attr   (zeros, EDGE_DIM=16)
//   [18E, 21E) rbf         exp(-d^2 / c^2), c in {4, 8, 12}
// E = 64 * 256 * 255 = 4,177,920.
//
// R2: output-centric mapping. One block = 256 consecutive edge ids; every
// store region is written with fully coalesced accesses (rbf staged via
// smem; zeros written as consecutive float4 per block). Removes the L1
// wavefront inflation that capped R1 at 76% L1 / 47% DRAM.

#define NPER    256
#define EPG     (NPER * (NPER - 1))      // 65280 edges per graph
#define E_TOTAL (64 * EPG)               // 4,177,920 = 16320 * 256

__global__ __launch_bounds__(256, 8)
void MultiScaleEdgeBuilder_kernel(const float* __restrict__ pos,
                                  float* __restrict__ out) {
    __shared__ __align__(16) float s_rbf[3 * 256];

    const int tid = threadIdx.x;
    const int e0  = blockIdx.x * 256;        // first edge of this block
    const int e   = e0 + tid;

    // ---- decompose edge id -> (g, i, j) --------------------------------
    int g  = e / EPG;                        // const-div -> mul.hi
    int r  = e - g * EPG;
    int i  = r / 255;
    int jp = r - i * 255;
    int j  = jp + (jp >= i);                 // skip diagonal

    int row = (g << 8) + i;
    int col = (g << 8) + j;

    // ---- compute rbf ----------------------------------------------------
    const float* pr = pos + 3 * row;         // warp-mostly-uniform, L1 hit
    const float* pc = pos + 3 * col;
    float dx = pr[0] - pc[0];
    float dy = pr[1] - pc[1];
    float dz = pr[2] - pc[2];
    float d2 = dx * dx + dy * dy + dz * dz;

    s_rbf[3 * tid + 0] = __expf(-d2 * (1.0f / 16.0f));   // c = 4
    s_rbf[3 * tid + 1] = __expf(-d2 * (1.0f / 64.0f));   // c = 8
    s_rbf[3 * tid + 2] = __expf(-d2 * (1.0f / 144.0f));  // c = 12

    // ---- edge_index: consecutive e -> perfectly coalesced ---------------
    out[e]           = (float)row;
    out[E_TOTAL + e] = (float)col;

    // ---- zeros: this block's 256*16 floats = 1024 float4, consecutive ---
    {
        float4 z = make_float4(0.f, 0.f, 0.f, 0.f);
        float4* zp = (float4*)(out + 2 * E_TOTAL + 16 * e0);
        #pragma unroll
        for (int k = 0; k < 4; k++)
            zp[tid + 256 * k] = z;           // coalesced 128B per warp-store
    }

    __syncthreads();

    // ---- rbf: 768 floats = 192 float4, coalesced from smem --------------
    if (tid < 192) {
        const float4* s4 = (const float4*)s_rbf;
        float4* rp = (float4*)(out + 18 * E_TOTAL + 3 * e0);
        rp[tid] = s4[tid];
    }
}

extern "C" void kernel_launch(void* const* d_in, const int* in_sizes, int n_in,
                              void* d_out, int out_size) {
    const float* pos = (const float*)d_in[0];   // [16384, 3] float32
    float* out = (float*)d_out;                 // 21 * E floats

    MultiScaleEdgeBuilder_kernel<<<E_TOTAL / 256, 256>>>(pos, out);
}